// round 1
// baseline (speedup 1.0000x reference)
#include <cuda_runtime.h>
#include <math_constants.h>

// Problem constants
#define BATCH   4
#define SEQ     1024
#define DMODEL  1024
#define NHEAD   16
#define DK      64
#define NBH     64          // BATCH*NHEAD
#define ROWS    4096        // BATCH*SEQ
#define HEAD_ELEMS 65536    // SEQ*DK, contiguous per-head slab
#define TEMPER_INV (1.0f/32.0f)   // 1/sqrt(DMODEL)

// ---------------- scratch (device globals, per allocation rules) ------------
__device__ float g_Q[ROWS * DMODEL];
__device__ float g_K[ROWS * DMODEL];
__device__ float g_V[ROWS * DMODEL];
__device__ float g_S[(long long)NBH * SEQ * SEQ];   // 256MB scores/probs
__device__ float g_AO[ROWS * DMODEL];               // attention output
__device__ float g_Y[ROWS * DMODEL];                // pre-LN

// ---------------- generic fp32 GEMM: C = A(MxK) * B(KxN) [+Res] -------------
// Row-major A, B, C. Optional batch strides via blockIdx.z. Optional causal
// K-clamp (K limited to rowTileEnd) for the PV GEMM.
#define GBM 128
#define GBN 64
#define GBK 16

__global__ __launch_bounds__(256) void gemm_kernel(
    const float* __restrict__ A, const float* __restrict__ B,
    float* __restrict__ C, const float* __restrict__ Res,
    int M, int N, int K,
    long long sA, long long sB, long long sC,
    int causal)
{
    A += (long long)blockIdx.z * sA;
    B += (long long)blockIdx.z * sB;
    C += (long long)blockIdx.z * sC;

    __shared__ float Ats[GBK][GBM + 4];   // k-major (transposed), padded: 16B-aligned rows
    __shared__ float Bs[GBK][GBN];

    const int tid = threadIdx.x;
    const int m0 = blockIdx.y * GBM;
    const int n0 = blockIdx.x * GBN;
    int kEnd = K;
    if (causal) { kEnd = m0 + GBM; if (kEnd > K) kEnd = K; }

    const int tx = tid & 15;       // 0..15  -> 4 cols
    const int ty = tid >> 4;       // 0..15  -> 8 rows
    const int ar  = tid >> 2;      // 0..63  (rows ar, ar+64)
    const int ac4 = tid & 3;       // float4 col in 16-wide K tile
    const int br  = tid >> 4;      // 0..15
    const int bc4 = tid & 15;      // float4 col in 64-wide N tile

    float acc[8][4] = {};

    for (int k0 = 0; k0 < kEnd; k0 += GBK) {
#pragma unroll
        for (int h = 0; h < 2; ++h) {
            int r = ar + 64 * h;
            float4 a = *(const float4*)&A[(long long)(m0 + r) * K + k0 + ac4 * 4];
            Ats[ac4 * 4 + 0][r] = a.x;
            Ats[ac4 * 4 + 1][r] = a.y;
            Ats[ac4 * 4 + 2][r] = a.z;
            Ats[ac4 * 4 + 3][r] = a.w;
        }
        *(float4*)&Bs[br][bc4 * 4] =
            *(const float4*)&B[(long long)(k0 + br) * N + n0 + bc4 * 4];
        __syncthreads();

#pragma unroll
        for (int k = 0; k < GBK; ++k) {
            float4 a0 = *(const float4*)&Ats[k][ty * 8];
            float4 a1 = *(const float4*)&Ats[k][ty * 8 + 4];
            float4 bb = *(const float4*)&Bs[k][tx * 4];
            float av[8] = {a0.x, a0.y, a0.z, a0.w, a1.x, a1.y, a1.z, a1.w};
            float bv[4] = {bb.x, bb.y, bb.z, bb.w};
#pragma unroll
            for (int i = 0; i < 8; ++i)
#pragma unroll
                for (int j = 0; j < 4; ++j)
                    acc[i][j] += av[i] * bv[j];
        }
        __syncthreads();
    }

#pragma unroll
    for (int i = 0; i < 8; ++i) {
        long long off = (long long)(m0 + ty * 8 + i) * N + n0 + tx * 4;
        float4 o = make_float4(acc[i][0], acc[i][1], acc[i][2], acc[i][3]);
        if (Res) {
            float4 r4 = *(const float4*)&Res[off];
            o.x += r4.x; o.y += r4.y; o.z += r4.z; o.w += r4.w;
        }
        *(float4*)&C[off] = o;
    }
}

// ---------------- scores: S[h] = Qh(1024x64) * Kh(1024x64)^T / 32 -----------
// 64x64 output tile per block, full K=64 in smem, causal tile skip.
__global__ __launch_bounds__(256) void scores_kernel(
    const float* __restrict__ Q, const float* __restrict__ Km,
    float* __restrict__ S)
{
    const int bx = blockIdx.x, by = blockIdx.y, h = blockIdx.z;
    if (bx > by) return;   // tile fully above diagonal -> fully masked

    __shared__ float Qts[DK][68];  // k-major, 272B rows (16B aligned)
    __shared__ float Kts[DK][68];

    const float* Qh = Q  + (long long)h * HEAD_ELEMS;
    const float* Kh = Km + (long long)h * HEAD_ELEMS;
    const int tid = threadIdx.x;
    const int r0 = by * 64, c0 = bx * 64;
    const int lr = tid >> 4;   // 0..15, 4 rows each
    const int c4 = tid & 15;   // float4 col

#pragma unroll
    for (int it = 0; it < 4; ++it) {
        int r = lr + 16 * it;
        float4 q4 = *(const float4*)&Qh[(long long)(r0 + r) * DK + c4 * 4];
        Qts[c4 * 4 + 0][r] = q4.x; Qts[c4 * 4 + 1][r] = q4.y;
        Qts[c4 * 4 + 2][r] = q4.z; Qts[c4 * 4 + 3][r] = q4.w;
        float4 k4 = *(const float4*)&Kh[(long long)(c0 + r) * DK + c4 * 4];
        Kts[c4 * 4 + 0][r] = k4.x; Kts[c4 * 4 + 1][r] = k4.y;
        Kts[c4 * 4 + 2][r] = k4.z; Kts[c4 * 4 + 3][r] = k4.w;
    }
    __syncthreads();

    const int tx = tid & 15, ty = tid >> 4;
    float acc[4][4] = {};
#pragma unroll
    for (int k = 0; k < DK; ++k) {
        float4 a = *(const float4*)&Qts[k][ty * 4];
        float4 b = *(const float4*)&Kts[k][tx * 4];
        float av[4] = {a.x, a.y, a.z, a.w};
        float bv[4] = {b.x, b.y, b.z, b.w};
#pragma unroll
        for (int i = 0; i < 4; ++i)
#pragma unroll
            for (int j = 0; j < 4; ++j)
                acc[i][j] += av[i] * bv[j];
    }

    float* Sh = S + (long long)h * SEQ * SEQ;
#pragma unroll
    for (int i = 0; i < 4; ++i) {
        float4 o = make_float4(acc[i][0] * TEMPER_INV, acc[i][1] * TEMPER_INV,
                               acc[i][2] * TEMPER_INV, acc[i][3] * TEMPER_INV);
        *(float4*)&Sh[(long long)(r0 + ty * 4 + i) * SEQ + c0 + tx * 4] = o;
    }
}

// ---------------- causal row softmax, in place; optional copy to d_out ------
__global__ __launch_bounds__(256) void softmax_kernel(
    float* __restrict__ S, float* __restrict__ attn_out)
{
    __shared__ float red[256];
    const int row = blockIdx.x;          // 0 .. NBH*SEQ-1
    const int l = row & (SEQ - 1);       // query position within head
    const int n = l + 1;                 // valid (causal) length
    const int tid = threadIdx.x;
    float* p = S + (long long)row * SEQ;

    float m = -CUDART_INF_F;
    for (int j = tid; j < n; j += 256) m = fmaxf(m, p[j]);
    red[tid] = m; __syncthreads();
    for (int s = 128; s > 0; s >>= 1) {
        if (tid < s) red[tid] = fmaxf(red[tid], red[tid + s]);
        __syncthreads();
    }
    const float rowmax = red[0];
    __syncthreads();

    float sum = 0.0f;
    for (int j = tid; j < n; j += 256) {
        float e = __expf(p[j] - rowmax);
        p[j] = e;
        sum += e;
    }
    red[tid] = sum; __syncthreads();
    for (int s = 128; s > 0; s >>= 1) {
        if (tid < s) red[tid] += red[tid + s];
        __syncthreads();
    }
    const float inv = 1.0f / red[0];
    __syncthreads();

    float* ap = attn_out ? attn_out + (long long)row * SEQ : nullptr;
    for (int j = tid; j < SEQ; j += 256) {
        float v = (j < n) ? p[j] * inv : 0.0f;
        p[j] = v;                       // zeros beyond l make PV K-clamp exact
        if (ap) ap[j] = v;
    }
}

// ---------------- LayerNorm over last dim (1024) ----------------------------
__global__ __launch_bounds__(256) void ln_kernel(
    const float* __restrict__ Y, const float* __restrict__ gg,
    const float* __restrict__ bb, float* __restrict__ out)
{
    __shared__ float red[256];
    const int row = blockIdx.x;
    const int tid = threadIdx.x;
    const float* x = Y + (long long)row * DMODEL;

    float s = 0.0f;
    for (int j = tid; j < DMODEL; j += 256) s += x[j];
    red[tid] = s; __syncthreads();
    for (int st = 128; st > 0; st >>= 1) {
        if (tid < st) red[tid] += red[tid + st];
        __syncthreads();
    }
    const float mu = red[0] * (1.0f / DMODEL);
    __syncthreads();

    float v = 0.0f;
    for (int j = tid; j < DMODEL; j += 256) {
        float d = x[j] - mu;
        v += d * d;
    }
    red[tid] = v; __syncthreads();
    for (int st = 128; st > 0; st >>= 1) {
        if (tid < st) red[tid] += red[tid + st];
        __syncthreads();
    }
    const float rstd = rsqrtf(red[0] * (1.0f / DMODEL) + 1e-6f);
    __syncthreads();

    float* o = out + (long long)row * DMODEL;
    for (int j = tid; j < DMODEL; j += 256)
        o[j] = (x[j] - mu) * rstd * gg[j] + bb[j];
}

// ---------------- launch ----------------------------------------------------
static float* symaddr(const void* sym) {
    void* p = nullptr;
    cudaGetSymbolAddress(&p, sym);
    return (float*)p;
}

extern "C" void kernel_launch(void* const* d_in, const int* in_sizes, int n_in,
                              void* d_out, int out_size)
{
    const float* q    = (const float*)d_in[0];
    const float* k    = (const float*)d_in[1];
    const float* v    = (const float*)d_in[2];
    const float* w_q  = (const float*)d_in[3];
    const float* w_k  = (const float*)d_in[4];
    const float* w_v  = (const float*)d_in[5];
    const float* w_o  = (const float*)d_in[6];
    const float* ln_g = (const float*)d_in[7];
    const float* ln_b = (const float*)d_in[8];
    // d_in[9] = attn_mask (pure causal; implemented analytically), d_in[10] = n_head

    float* out = (float*)d_out;
    float* attn_out = nullptr;
    const long long OUT_ELEMS  = (long long)ROWS * DMODEL;          // 4,194,304
    const long long ATTN_ELEMS = (long long)NBH * SEQ * SEQ;        // 67,108,864
    if ((long long)out_size >= OUT_ELEMS + ATTN_ELEMS)
        attn_out = out + OUT_ELEMS;

    float* Q  = symaddr(g_Q);
    float* K  = symaddr(g_K);
    float* V  = symaddr(g_V);
    float* S  = symaddr(g_S);
    float* AO = symaddr(g_AO);
    float* Y  = symaddr(g_Y);

    // 1-3. QKV projections: (4096x1024) @ (1024x1024)
    dim3 gProj(DMODEL / GBN, ROWS / GBM, 1);
    gemm_kernel<<<gProj, 256>>>(q, w_q, Q, nullptr, ROWS, DMODEL, DMODEL, 0, 0, 0, 0);
    gemm_kernel<<<gProj, 256>>>(k, w_k, K, nullptr, ROWS, DMODEL, DMODEL, 0, 0, 0, 0);
    gemm_kernel<<<gProj, 256>>>(v, w_v, V, nullptr, ROWS, DMODEL, DMODEL, 0, 0, 0, 0);

    // 4. scores (causal tiles only)
    dim3 gS(SEQ / 64, SEQ / 64, NBH);
    scores_kernel<<<gS, 256>>>(Q, K, S);

    // 5. softmax (in place; optional copy of probs to output)
    softmax_kernel<<<NBH * SEQ, 256>>>(S, attn_out);

    // 6. PV: per head (1024x1024) @ (1024x64) with causal K-clamp
    dim3 gPV(DK / GBN, SEQ / GBM, NBH);
    gemm_kernel<<<gPV, 256>>>(S, V, AO, nullptr, SEQ, DK, SEQ,
                              (long long)SEQ * SEQ, HEAD_ELEMS, HEAD_ELEMS, 1);

    // 7. output projection + residual
    gemm_kernel<<<gProj, 256>>>(AO, w_o, Y, q, ROWS, DMODEL, DMODEL, 0, 0, 0, 0);

    // 8. LayerNorm -> d_out
    ln_kernel<<<ROWS, 256>>>(Y, ln_g, ln_b, out);
}

// round 2
// speedup vs baseline: 2.7327x; 2.7327x over previous
#include <cuda_runtime.h>
#include <math_constants.h>

// Problem constants
#define BATCH   4
#define SEQ     1024
#define DMODEL  1024
#define NHEAD   16
#define DK      64
#define NBH     64          // BATCH*NHEAD
#define ROWS    4096        // BATCH*SEQ
#define HEAD_ELEMS 65536    // SEQ*DK, contiguous per-head slab
#define TEMPER_INV (1.0f/32.0f)   // 1/sqrt(DMODEL)

// ---------------- scratch (device globals) ----------------------------------
__device__ float g_Q[ROWS * DMODEL];
__device__ float g_K[ROWS * DMODEL];
__device__ float g_V[ROWS * DMODEL];
__device__ float g_S[(long long)NBH * SEQ * SEQ];   // raw scores
__device__ float g_AO[ROWS * DMODEL];               // attention output
__device__ float g_Y[ROWS * DMODEL];                // pre-LN

// ---------------- tf32 helpers ----------------------------------------------
__device__ __forceinline__ unsigned f2tf(float x) {
    unsigned r;
    asm("cvt.rna.tf32.f32 %0, %1;" : "=r"(r) : "f"(x));
    return r;
}

__device__ __forceinline__ void mma8(float* c, const unsigned* a, const unsigned* b) {
    asm volatile(
        "mma.sync.aligned.m16n8k8.row.col.f32.tf32.tf32.f32 "
        "{%0,%1,%2,%3},{%4,%5,%6,%7},{%8,%9},{%0,%1,%2,%3};"
        : "+f"(c[0]), "+f"(c[1]), "+f"(c[2]), "+f"(c[3])
        : "r"(a[0]), "r"(a[1]), "r"(a[2]), "r"(a[3]), "r"(b[0]), "r"(b[1]));
}

// ---------------- tensor-core NN GEMM: C = A(MxK) @ B(KxN) [+Res] ------------
// BM=128, BK=32 fixed. 256 threads = 8 warps as 4(m) x 2(n).
// As stride 36 and Bs stride BN+4 are ≡4 (mod 32) -> conflict-free frag LDS.
template<int BN, bool CAUSAL, bool RES>
__global__ __launch_bounds__(256, 2) void gemm_tc(
    const float* __restrict__ A, const float* __restrict__ B,
    float* __restrict__ C, const float* __restrict__ Res,
    int M, int N, int K, long long sA, long long sB, long long sC)
{
    constexpr int BM = 128, BK = 32;
    constexpr int WN = BN / 2;        // warp n-extent
    constexpr int NT = WN / 8;        // n-tiles per warp
    __shared__ unsigned As[BM][BK + 4];
    __shared__ unsigned Bs[BK][BN + 4];

    A += (long long)blockIdx.z * sA;
    B += (long long)blockIdx.z * sB;
    C += (long long)blockIdx.z * sC;

    const int tid  = threadIdx.x;
    const int lane = tid & 31;
    const int warp = tid >> 5;
    const int wm   = (warp & 3) * 32;
    const int wn   = (warp >> 2) * WN;
    const int m0   = blockIdx.y * BM;
    const int n0   = blockIdx.x * BN;
    int kEnd = K;
    if (CAUSAL) { kEnd = m0 + BM; if (kEnd > K) kEnd = K; }

    float acc[2][NT][4];
#pragma unroll
    for (int i = 0; i < 2; ++i)
#pragma unroll
        for (int j = 0; j < NT; ++j)
#pragma unroll
            for (int q = 0; q < 4; ++q) acc[i][j][q] = 0.0f;

    for (int k0 = 0; k0 < kEnd; k0 += BK) {
        // A tile: 128x32 = 1024 float4, 4 per thread
#pragma unroll
        for (int i = 0; i < 4; ++i) {
            int idx = tid + i * 256;
            int r = idx >> 3, c4 = (idx & 7) * 4;
            float4 v = *(const float4*)&A[(long long)(m0 + r) * K + k0 + c4];
            As[r][c4 + 0] = f2tf(v.x); As[r][c4 + 1] = f2tf(v.y);
            As[r][c4 + 2] = f2tf(v.z); As[r][c4 + 3] = f2tf(v.w);
        }
        // B tile: 32xBN
#pragma unroll
        for (int i = 0; i < (BK * BN / 4) / 256; ++i) {
            int idx = tid + i * 256;
            int r = idx / (BN / 4), c4 = (idx % (BN / 4)) * 4;
            float4 v = *(const float4*)&B[(long long)(k0 + r) * N + n0 + c4];
            Bs[r][c4 + 0] = f2tf(v.x); Bs[r][c4 + 1] = f2tf(v.y);
            Bs[r][c4 + 2] = f2tf(v.z); Bs[r][c4 + 3] = f2tf(v.w);
        }
        __syncthreads();

#pragma unroll
        for (int kk = 0; kk < 4; ++kk) {
            const int ks = kk * 8;
            unsigned af[2][4];
#pragma unroll
            for (int mt = 0; mt < 2; ++mt) {
                int m = wm + mt * 16 + (lane >> 2);
                af[mt][0] = As[m][ks + (lane & 3)];
                af[mt][1] = As[m + 8][ks + (lane & 3)];
                af[mt][2] = As[m][ks + 4 + (lane & 3)];
                af[mt][3] = As[m + 8][ks + 4 + (lane & 3)];
            }
            unsigned bf[NT][2];
#pragma unroll
            for (int nt = 0; nt < NT; ++nt) {
                int n = wn + nt * 8 + (lane >> 2);
                bf[nt][0] = Bs[ks + (lane & 3)][n];
                bf[nt][1] = Bs[ks + 4 + (lane & 3)][n];
            }
#pragma unroll
            for (int mt = 0; mt < 2; ++mt)
#pragma unroll
                for (int nt = 0; nt < NT; ++nt)
                    mma8(acc[mt][nt], af[mt], bf[nt]);
        }
        __syncthreads();
    }

    // epilogue
#pragma unroll
    for (int mt = 0; mt < 2; ++mt) {
#pragma unroll
        for (int nt = 0; nt < NT; ++nt) {
            int r = m0 + wm + mt * 16 + (lane >> 2);
            int c = n0 + wn + nt * 8 + 2 * (lane & 3);
            long long o0 = (long long)r * N + c;
            long long o1 = (long long)(r + 8) * N + c;
            float2 v0 = make_float2(acc[mt][nt][0], acc[mt][nt][1]);
            float2 v1 = make_float2(acc[mt][nt][2], acc[mt][nt][3]);
            if (RES) {
                float2 r0 = *(const float2*)&Res[o0];
                float2 r1 = *(const float2*)&Res[o1];
                v0.x += r0.x; v0.y += r0.y; v1.x += r1.x; v1.y += r1.y;
            }
            *(float2*)&C[o0] = v0;
            *(float2*)&C[o1] = v1;
        }
    }
}

// ---------------- scores (NT): S[h] = Qh @ Kh^T / 32, causal tile skip ------
// Both Q and K head slabs are row-major [1024][64]; with Ks stored natural,
// B[k][n] = Ks[n][k] -> NT gemm with no transposes. Dynamic smem (69.6KB).
__global__ __launch_bounds__(256) void scores_tc(
    const float* __restrict__ Q, const float* __restrict__ Km,
    float* __restrict__ S)
{
    const int bx = blockIdx.x, by = blockIdx.y, h = blockIdx.z;
    if (bx > by) return;

    extern __shared__ unsigned sm[];
    unsigned (*Qs)[68] = (unsigned(*)[68])sm;
    unsigned (*Ks)[68] = (unsigned(*)[68])(sm + 128 * 68);

    const float* Qh = Q  + (long long)h * HEAD_ELEMS;
    const float* Kh = Km + (long long)h * HEAD_ELEMS;
    const int tid  = threadIdx.x;
    const int lane = tid & 31;
    const int warp = tid >> 5;
    const int wm   = (warp & 3) * 32;
    const int wn   = (warp >> 2) * 64;
    const int r0   = by * 128, c0 = bx * 128;

    // load tiles: 128 rows x 16 float4 each
#pragma unroll
    for (int i = 0; i < 8; ++i) {
        int idx = tid + i * 256;
        int r = idx >> 4, c4 = (idx & 15) * 4;
        float4 q4 = *(const float4*)&Qh[(long long)(r0 + r) * DK + c4];
        Qs[r][c4 + 0] = f2tf(q4.x); Qs[r][c4 + 1] = f2tf(q4.y);
        Qs[r][c4 + 2] = f2tf(q4.z); Qs[r][c4 + 3] = f2tf(q4.w);
        float4 k4 = *(const float4*)&Kh[(long long)(c0 + r) * DK + c4];
        Ks[r][c4 + 0] = f2tf(k4.x); Ks[r][c4 + 1] = f2tf(k4.y);
        Ks[r][c4 + 2] = f2tf(k4.z); Ks[r][c4 + 3] = f2tf(k4.w);
    }
    __syncthreads();

    float acc[2][8][4];
#pragma unroll
    for (int i = 0; i < 2; ++i)
#pragma unroll
        for (int j = 0; j < 8; ++j)
#pragma unroll
            for (int q = 0; q < 4; ++q) acc[i][j][q] = 0.0f;

#pragma unroll
    for (int kk = 0; kk < 8; ++kk) {
        const int ks = kk * 8;
        unsigned af[2][4];
#pragma unroll
        for (int mt = 0; mt < 2; ++mt) {
            int m = wm + mt * 16 + (lane >> 2);
            af[mt][0] = Qs[m][ks + (lane & 3)];
            af[mt][1] = Qs[m + 8][ks + (lane & 3)];
            af[mt][2] = Qs[m][ks + 4 + (lane & 3)];
            af[mt][3] = Qs[m + 8][ks + 4 + (lane & 3)];
        }
        unsigned bf[8][2];
#pragma unroll
        for (int nt = 0; nt < 8; ++nt) {
            int n = wn + nt * 8 + (lane >> 2);
            bf[nt][0] = Ks[n][ks + (lane & 3)];
            bf[nt][1] = Ks[n][ks + 4 + (lane & 3)];
        }
#pragma unroll
        for (int mt = 0; mt < 2; ++mt)
#pragma unroll
            for (int nt = 0; nt < 8; ++nt)
                mma8(acc[mt][nt], af[mt], bf[nt]);
    }

    float* Sh = S + (long long)h * SEQ * SEQ;
#pragma unroll
    for (int mt = 0; mt < 2; ++mt) {
#pragma unroll
        for (int nt = 0; nt < 8; ++nt) {
            int r = r0 + wm + mt * 16 + (lane >> 2);
            int c = c0 + wn + nt * 8 + 2 * (lane & 3);
            float2 v0 = make_float2(acc[mt][nt][0] * TEMPER_INV, acc[mt][nt][1] * TEMPER_INV);
            float2 v1 = make_float2(acc[mt][nt][2] * TEMPER_INV, acc[mt][nt][3] * TEMPER_INV);
            *(float2*)&Sh[(long long)r * SEQ + c] = v0;
            *(float2*)&Sh[(long long)(r + 8) * SEQ + c] = v1;
        }
    }
}

// ---------------- causal row softmax: raw scores -> probs (dst) --------------
__global__ __launch_bounds__(256) void softmax_kernel(
    const float* __restrict__ S, float* __restrict__ dst)
{
    __shared__ float red[8];
    const int row = blockIdx.x;
    const int l = row & (SEQ - 1);
    const int tid = threadIdx.x;
    const int lane = tid & 31, warp = tid >> 5;
    const float4 sv = ((const float4*)(S + (long long)row * SEQ))[tid];
    const int j0 = tid * 4;
    float v[4] = {sv.x, sv.y, sv.z, sv.w};

    float m = -CUDART_INF_F;
#pragma unroll
    for (int i = 0; i < 4; ++i) if (j0 + i <= l) m = fmaxf(m, v[i]);
#pragma unroll
    for (int s = 16; s > 0; s >>= 1) m = fmaxf(m, __shfl_xor_sync(~0u, m, s));
    if (lane == 0) red[warp] = m;
    __syncthreads();
    if (warp == 0) {
        float t = red[lane & 7];
#pragma unroll
        for (int s = 4; s > 0; s >>= 1) t = fmaxf(t, __shfl_xor_sync(~0u, t, s));
        if (lane == 0) red[0] = t;
    }
    __syncthreads();
    const float rowmax = red[0];
    __syncthreads();

    float e[4], sum = 0.0f;
#pragma unroll
    for (int i = 0; i < 4; ++i) {
        e[i] = (j0 + i <= l) ? __expf(v[i] - rowmax) : 0.0f;
        sum += e[i];
    }
#pragma unroll
    for (int s = 16; s > 0; s >>= 1) sum += __shfl_xor_sync(~0u, sum, s);
    if (lane == 0) red[warp] = sum;
    __syncthreads();
    if (warp == 0) {
        float t = red[lane & 7];
#pragma unroll
        for (int s = 4; s > 0; s >>= 1) t += __shfl_xor_sync(~0u, t, s);
        if (lane == 0) red[0] = t;
    }
    __syncthreads();
    const float inv = 1.0f / red[0];

    float4 o = make_float4(e[0] * inv, e[1] * inv, e[2] * inv, e[3] * inv);
    ((float4*)(dst + (long long)row * SEQ))[tid] = o;
}

// ---------------- LayerNorm over last dim (1024) -----------------------------
__global__ __launch_bounds__(256) void ln_kernel(
    const float* __restrict__ Y, const float* __restrict__ gg,
    const float* __restrict__ bb, float* __restrict__ out)
{
    __shared__ float red[8];
    const int row = blockIdx.x;
    const int tid = threadIdx.x;
    const int lane = tid & 31, warp = tid >> 5;
    const float4 xv = ((const float4*)(Y + (long long)row * DMODEL))[tid];
    float v[4] = {xv.x, xv.y, xv.z, xv.w};

    float s = v[0] + v[1] + v[2] + v[3];
#pragma unroll
    for (int st = 16; st > 0; st >>= 1) s += __shfl_xor_sync(~0u, s, st);
    if (lane == 0) red[warp] = s;
    __syncthreads();
    if (warp == 0) {
        float t = red[lane & 7];
#pragma unroll
        for (int st = 4; st > 0; st >>= 1) t += __shfl_xor_sync(~0u, t, st);
        if (lane == 0) red[0] = t;
    }
    __syncthreads();
    const float mu = red[0] * (1.0f / DMODEL);
    __syncthreads();

    float var = 0.0f;
#pragma unroll
    for (int i = 0; i < 4; ++i) { float d = v[i] - mu; var += d * d; }
#pragma unroll
    for (int st = 16; st > 0; st >>= 1) var += __shfl_xor_sync(~0u, var, st);
    if (lane == 0) red[warp] = var;
    __syncthreads();
    if (warp == 0) {
        float t = red[lane & 7];
#pragma unroll
        for (int st = 4; st > 0; st >>= 1) t += __shfl_xor_sync(~0u, t, st);
        if (lane == 0) red[0] = t;
    }
    __syncthreads();
    const float rstd = rsqrtf(red[0] * (1.0f / DMODEL) + 1e-6f);

    const float4 g4 = ((const float4*)gg)[tid];
    const float4 b4 = ((const float4*)bb)[tid];
    float4 o;
    o.x = (v[0] - mu) * rstd * g4.x + b4.x;
    o.y = (v[1] - mu) * rstd * g4.y + b4.y;
    o.z = (v[2] - mu) * rstd * g4.z + b4.z;
    o.w = (v[3] - mu) * rstd * g4.w + b4.w;
    ((float4*)(out + (long long)row * DMODEL))[tid] = o;
}

// ---------------- launch -----------------------------------------------------
static float* symaddr(const void* sym) {
    void* p = nullptr;
    cudaGetSymbolAddress(&p, sym);
    return (float*)p;
}

extern "C" void kernel_launch(void* const* d_in, const int* in_sizes, int n_in,
                              void* d_out, int out_size)
{
    const float* q    = (const float*)d_in[0];
    const float* k    = (const float*)d_in[1];
    const float* v    = (const float*)d_in[2];
    const float* w_q  = (const float*)d_in[3];
    const float* w_k  = (const float*)d_in[4];
    const float* w_v  = (const float*)d_in[5];
    const float* w_o  = (const float*)d_in[6];
    const float* ln_g = (const float*)d_in[7];
    const float* ln_b = (const float*)d_in[8];

    float* out = (float*)d_out;
    float* attn_out = nullptr;
    const long long OUT_ELEMS  = (long long)ROWS * DMODEL;
    const long long ATTN_ELEMS = (long long)NBH * SEQ * SEQ;
    if ((long long)out_size >= OUT_ELEMS + ATTN_ELEMS)
        attn_out = out + OUT_ELEMS;

    float* Q  = symaddr(g_Q);
    float* K  = symaddr(g_K);
    float* V  = symaddr(g_V);
    float* S  = symaddr(g_S);
    float* AO = symaddr(g_AO);
    float* Y  = symaddr(g_Y);

    static bool attr_done = false;
    if (!attr_done) {
        cudaFuncSetAttribute(scores_tc,
                             cudaFuncAttributeMaxDynamicSharedMemorySize,
                             2 * 128 * 68 * 4);
        attr_done = true;
    }

    // 1-3. QKV projections: (4096x1024) @ (1024x1024)
    dim3 gProj(DMODEL / 128, ROWS / 128, 1);
    gemm_tc<128, false, false><<<gProj, 256>>>(q, w_q, Q, nullptr, ROWS, DMODEL, DMODEL, 0, 0, 0);
    gemm_tc<128, false, false><<<gProj, 256>>>(k, w_k, K, nullptr, ROWS, DMODEL, DMODEL, 0, 0, 0);
    gemm_tc<128, false, false><<<gProj, 256>>>(v, w_v, V, nullptr, ROWS, DMODEL, DMODEL, 0, 0, 0);

    // 4. scores (causal tiles only)
    dim3 gS(SEQ / 128, SEQ / 128, NBH);
    scores_tc<<<gS, 256, 2 * 128 * 68 * 4>>>(Q, K, S);

    // 5. softmax: raw scores -> probs (directly into output attn region if present)
    float* probs = attn_out ? attn_out : S;
    softmax_kernel<<<NBH * SEQ, 256>>>(S, probs);

    // 6. PV: per head (1024x1024) @ (1024x64), causal K-clamp
    dim3 gPV(1, SEQ / 128, NBH);
    gemm_tc<64, true, false><<<gPV, 256>>>(probs, V, AO, nullptr, SEQ, DK, SEQ,
                                           (long long)SEQ * SEQ, HEAD_ELEMS, HEAD_ELEMS);

    // 7. output projection + residual
    gemm_tc<128, false, true><<<gProj, 256>>>(AO, w_o, Y, q, ROWS, DMODEL, DMODEL, 0, 0, 0);

    // 8. LayerNorm -> d_out
    ln_kernel<<<ROWS, 256>>>(Y, ln_g, ln_b, out);
}

// round 3
// speedup vs baseline: 3.0732x; 1.1246x over previous
#include <cuda_runtime.h>
#include <cuda_bf16.h>
#include <math_constants.h>

// Problem constants
#define BATCH   4
#define SEQ     1024
#define DMODEL  1024
#define NHEAD   16
#define DK      64
#define NBH     64
#define ROWS    4096
#define HEAD_ELEMS 65536
#define TEMPER_INV (1.0f/32.0f)

// ---------------- scratch ----------------------------------------------------
__device__ float g_Q[ROWS * DMODEL];
__device__ float g_K[ROWS * DMODEL];
__device__ float g_V[ROWS * DMODEL];
__device__ float g_S[(long long)NBH * SEQ * SEQ];
__device__ float g_AO[ROWS * DMODEL];
__device__ float g_Y[ROWS * DMODEL];

// ---------------- helpers ----------------------------------------------------
__device__ __forceinline__ unsigned bf2pack(float x, float y) {
    unsigned r;
    asm("cvt.rn.bf16x2.f32 %0, %2, %1;" : "=r"(r) : "f"(x), "f"(y));
    return r;   // low half = x, high half = y
}

__device__ __forceinline__ unsigned sptr(const void* p) {
    return (unsigned)__cvta_generic_to_shared(p);
}

__device__ __forceinline__ void ldsm4(unsigned& r0, unsigned& r1, unsigned& r2, unsigned& r3, unsigned addr) {
    asm volatile("ldmatrix.sync.aligned.m8n8.x4.shared.b16 {%0,%1,%2,%3}, [%4];"
                 : "=r"(r0), "=r"(r1), "=r"(r2), "=r"(r3) : "r"(addr));
}

__device__ __forceinline__ void ldsm4t(unsigned& r0, unsigned& r1, unsigned& r2, unsigned& r3, unsigned addr) {
    asm volatile("ldmatrix.sync.aligned.m8n8.x4.trans.shared.b16 {%0,%1,%2,%3}, [%4];"
                 : "=r"(r0), "=r"(r1), "=r"(r2), "=r"(r3) : "r"(addr));
}

__device__ __forceinline__ void mma16(float* c, const unsigned* a, const unsigned* b) {
    asm volatile(
        "mma.sync.aligned.m16n8k16.row.col.f32.bf16.bf16.f32 "
        "{%0,%1,%2,%3},{%4,%5,%6,%7},{%8,%9},{%0,%1,%2,%3};"
        : "+f"(c[0]), "+f"(c[1]), "+f"(c[2]), "+f"(c[3])
        : "r"(a[0]), "r"(a[1]), "r"(a[2]), "r"(a[3]), "r"(b[0]), "r"(b[1]));
}

// ---------------- bf16 tensor-core NN GEMM: C = A @ B [+Res] -----------------
// BM=128, BK=32, 256 threads = 8 warps (4m x 2n). Double-buffered smem with
// register prefetch of the next k-tile. ldmatrix strides: As 40, Bs BN+8.
template<int BN, bool CAUSAL, bool RES>
__global__ __launch_bounds__(256) void gemm_bf16(
    const float* __restrict__ A, const float* __restrict__ B,
    float* __restrict__ C, const float* __restrict__ Res,
    int M, int N, int K, long long sA, long long sB, long long sC)
{
    constexpr int BM = 128, BK = 32;
    constexpr int SA = BK + 8;        // 40 halves: row bank start 20r mod 32, conflict-free
    constexpr int SB = BN + 8;        // 136/72 halves: 4r mod 32, conflict-free
    constexpr int NT = (BN / 2) / 8;  // n-tiles per warp (8 or 4)
    constexpr int NB4 = BK * BN / 4 / 256;  // B float4 loads per thread (4 or 2)

    __shared__ __nv_bfloat16 As[2][BM][SA];
    __shared__ __nv_bfloat16 Bs[2][BK][SB];

    A += (long long)blockIdx.z * sA;
    B += (long long)blockIdx.z * sB;
    C += (long long)blockIdx.z * sC;

    const int tid  = threadIdx.x;
    const int lane = tid & 31;
    const int warp = tid >> 5;
    const int wm   = (warp & 3) * 32;
    const int wn   = (warp >> 2) * (BN / 2);
    const int m0   = blockIdx.y * BM;
    const int n0   = blockIdx.x * BN;
    int kEnd = K;
    if (CAUSAL) { kEnd = m0 + BM; if (kEnd > K) kEnd = K; }

    const int ar  = tid >> 3;            // A: row 0..127 (x4 iters: +0 only.. see below)
    const int ac4 = (tid & 7) * 4;

    float4 pa[4], pb[NB4];

    auto gloadA = [&](int k0) {
#pragma unroll
        for (int i = 0; i < 4; ++i) {
            int idx = tid + i * 256;
            int r = idx >> 3, c4 = (idx & 7) * 4;
            pa[i] = *(const float4*)&A[(long long)(m0 + r) * K + k0 + c4];
        }
    };
    auto gloadB = [&](int k0) {
#pragma unroll
        for (int i = 0; i < NB4; ++i) {
            int idx = tid + i * 256;
            int r = idx / (BN / 4), c4 = (idx % (BN / 4)) * 4;
            pb[i] = *(const float4*)&B[(long long)(k0 + r) * N + n0 + c4];
        }
    };
    auto sstore = [&](int buf) {
#pragma unroll
        for (int i = 0; i < 4; ++i) {
            int idx = tid + i * 256;
            int r = idx >> 3, c4 = (idx & 7) * 4;
            uint2 u = make_uint2(bf2pack(pa[i].x, pa[i].y), bf2pack(pa[i].z, pa[i].w));
            *(uint2*)&As[buf][r][c4] = u;
        }
#pragma unroll
        for (int i = 0; i < NB4; ++i) {
            int idx = tid + i * 256;
            int r = idx / (BN / 4), c4 = (idx % (BN / 4)) * 4;
            uint2 u = make_uint2(bf2pack(pb[i].x, pb[i].y), bf2pack(pb[i].z, pb[i].w));
            *(uint2*)&Bs[buf][r][c4] = u;
        }
    };

    float acc[2][NT][4];
#pragma unroll
    for (int i = 0; i < 2; ++i)
#pragma unroll
        for (int j = 0; j < NT; ++j)
#pragma unroll
            for (int q = 0; q < 4; ++q) acc[i][j][q] = 0.0f;

    auto compute = [&](int buf) {
#pragma unroll
        for (int ks = 0; ks < BK; ks += 16) {
            unsigned af[2][4];
#pragma unroll
            for (int mt = 0; mt < 2; ++mt)
                ldsm4(af[mt][0], af[mt][1], af[mt][2], af[mt][3],
                      sptr(&As[buf][wm + mt * 16 + (lane & 15)][ks + 8 * (lane >> 4)]));
            unsigned bf[NT][2];
#pragma unroll
            for (int nn = 0; nn < NT / 2; ++nn) {
                unsigned r0, r1, r2, r3;
                ldsm4t(r0, r1, r2, r3,
                       sptr(&Bs[buf][ks + (lane & 15)][wn + nn * 16 + 8 * (lane >> 4)]));
                bf[nn * 2][0] = r0; bf[nn * 2][1] = r1;
                bf[nn * 2 + 1][0] = r2; bf[nn * 2 + 1][1] = r3;
            }
#pragma unroll
            for (int mt = 0; mt < 2; ++mt)
#pragma unroll
                for (int nt = 0; nt < NT; ++nt)
                    mma16(acc[mt][nt], af[mt], bf[nt]);
        }
    };

    gloadA(0); gloadB(0);
    sstore(0);
    __syncthreads();
    int buf = 0;
    for (int k0 = BK; k0 < kEnd; k0 += BK) {
        gloadA(k0); gloadB(k0);
        compute(buf);
        sstore(buf ^ 1);
        __syncthreads();
        buf ^= 1;
    }
    compute(buf);

    // epilogue
#pragma unroll
    for (int mt = 0; mt < 2; ++mt) {
#pragma unroll
        for (int nt = 0; nt < NT; ++nt) {
            int r = m0 + wm + mt * 16 + (lane >> 2);
            int c = n0 + wn + nt * 8 + 2 * (lane & 3);
            long long o0 = (long long)r * N + c;
            long long o1 = (long long)(r + 8) * N + c;
            float2 v0 = make_float2(acc[mt][nt][0], acc[mt][nt][1]);
            float2 v1 = make_float2(acc[mt][nt][2], acc[mt][nt][3]);
            if (RES) {
                float2 r0 = *(const float2*)&Res[o0];
                float2 r1 = *(const float2*)&Res[o1];
                v0.x += r0.x; v0.y += r0.y; v1.x += r1.x; v1.y += r1.y;
            }
            *(float2*)&C[o0] = v0;
            *(float2*)&C[o1] = v1;
        }
    }
}

// ---------------- scores (NT): S[h] = Qh @ Kh^T / 32, causal tile skip -------
__global__ __launch_bounds__(256) void scores_bf16(
    const float* __restrict__ Q, const float* __restrict__ Km,
    float* __restrict__ S)
{
    const int bx = blockIdx.x, by = blockIdx.y, h = blockIdx.z;
    if (bx > by) return;

    constexpr int ST = DK + 8;   // 72 halves: 4r mod 32 bank starts, conflict-free
    __shared__ __nv_bfloat16 Qs[128][ST];
    __shared__ __nv_bfloat16 Ks[128][ST];

    const float* Qh = Q  + (long long)h * HEAD_ELEMS;
    const float* Kh = Km + (long long)h * HEAD_ELEMS;
    const int tid  = threadIdx.x;
    const int lane = tid & 31;
    const int warp = tid >> 5;
    const int wm   = (warp & 3) * 32;
    const int wn   = (warp >> 2) * 64;
    const int r0   = by * 128, c0 = bx * 128;

#pragma unroll
    for (int i = 0; i < 8; ++i) {
        int idx = tid + i * 256;
        int r = idx >> 4, c4 = (idx & 15) * 4;
        float4 q4 = *(const float4*)&Qh[(long long)(r0 + r) * DK + c4];
        *(uint2*)&Qs[r][c4] = make_uint2(bf2pack(q4.x, q4.y), bf2pack(q4.z, q4.w));
        float4 k4 = *(const float4*)&Kh[(long long)(c0 + r) * DK + c4];
        *(uint2*)&Ks[r][c4] = make_uint2(bf2pack(k4.x, k4.y), bf2pack(k4.z, k4.w));
    }
    __syncthreads();

    float acc[2][8][4];
#pragma unroll
    for (int i = 0; i < 2; ++i)
#pragma unroll
        for (int j = 0; j < 8; ++j)
#pragma unroll
            for (int q = 0; q < 4; ++q) acc[i][j][q] = 0.0f;

#pragma unroll
    for (int ks = 0; ks < DK; ks += 16) {
        unsigned af[2][4];
#pragma unroll
        for (int mt = 0; mt < 2; ++mt)
            ldsm4(af[mt][0], af[mt][1], af[mt][2], af[mt][3],
                  sptr(&Qs[wm + mt * 16 + (lane & 15)][ks + 8 * (lane >> 4)]));
        // B from n-major K: non-trans x4 -> matrices (n0-7,k0-7),(n8-15,k0-7),
        // (n0-7,k8-15),(n8-15,k8-15): ntile0={r0,r2}, ntile1={r1,r3}
        unsigned bf[8][2];
#pragma unroll
        for (int nn = 0; nn < 4; ++nn) {
            unsigned q0, q1, q2, q3;
            ldsm4(q0, q1, q2, q3,
                  sptr(&Ks[wn + nn * 16 + (lane & 15)][ks + 8 * (lane >> 4)]));
            bf[nn * 2][0] = q0; bf[nn * 2][1] = q2;
            bf[nn * 2 + 1][0] = q1; bf[nn * 2 + 1][1] = q3;
        }
#pragma unroll
        for (int mt = 0; mt < 2; ++mt)
#pragma unroll
            for (int nt = 0; nt < 8; ++nt)
                mma16(acc[mt][nt], af[mt], bf[nt]);
    }

    float* Sh = S + (long long)h * SEQ * SEQ;
#pragma unroll
    for (int mt = 0; mt < 2; ++mt) {
#pragma unroll
        for (int nt = 0; nt < 8; ++nt) {
            int r = r0 + wm + mt * 16 + (lane >> 2);
            int c = c0 + wn + nt * 8 + 2 * (lane & 3);
            float2 v0 = make_float2(acc[mt][nt][0] * TEMPER_INV, acc[mt][nt][1] * TEMPER_INV);
            float2 v1 = make_float2(acc[mt][nt][2] * TEMPER_INV, acc[mt][nt][3] * TEMPER_INV);
            *(float2*)&Sh[(long long)r * SEQ + c] = v0;
            *(float2*)&Sh[(long long)(r + 8) * SEQ + c] = v1;
        }
    }
}

// ---------------- causal row softmax -----------------------------------------
__global__ __launch_bounds__(256) void softmax_kernel(
    const float* __restrict__ S, float* __restrict__ dst)
{
    __shared__ float red[8];
    const int row = blockIdx.x;
    const int l = row & (SEQ - 1);
    const int tid = threadIdx.x;
    const int lane = tid & 31, warp = tid >> 5;
    const float4 sv = ((const float4*)(S + (long long)row * SEQ))[tid];
    const int j0 = tid * 4;
    float v[4] = {sv.x, sv.y, sv.z, sv.w};

    float m = -CUDART_INF_F;
#pragma unroll
    for (int i = 0; i < 4; ++i) if (j0 + i <= l) m = fmaxf(m, v[i]);
#pragma unroll
    for (int s = 16; s > 0; s >>= 1) m = fmaxf(m, __shfl_xor_sync(~0u, m, s));
    if (lane == 0) red[warp] = m;
    __syncthreads();
    if (warp == 0) {
        float t = red[lane & 7];
#pragma unroll
        for (int s = 4; s > 0; s >>= 1) t = fmaxf(t, __shfl_xor_sync(~0u, t, s));
        if (lane == 0) red[0] = t;
    }
    __syncthreads();
    const float rowmax = red[0];
    __syncthreads();

    float e[4], sum = 0.0f;
#pragma unroll
    for (int i = 0; i < 4; ++i) {
        e[i] = (j0 + i <= l) ? __expf(v[i] - rowmax) : 0.0f;
        sum += e[i];
    }
#pragma unroll
    for (int s = 16; s > 0; s >>= 1) sum += __shfl_xor_sync(~0u, sum, s);
    if (lane == 0) red[warp] = sum;
    __syncthreads();
    if (warp == 0) {
        float t = red[lane & 7];
#pragma unroll
        for (int s = 4; s > 0; s >>= 1) t += __shfl_xor_sync(~0u, t, s);
        if (lane == 0) red[0] = t;
    }
    __syncthreads();
    const float inv = 1.0f / red[0];

    float4 o = make_float4(e[0] * inv, e[1] * inv, e[2] * inv, e[3] * inv);
    ((float4*)(dst + (long long)row * SEQ))[tid] = o;
}

// ---------------- LayerNorm --------------------------------------------------
__global__ __launch_bounds__(256) void ln_kernel(
    const float* __restrict__ Y, const float* __restrict__ gg,
    const float* __restrict__ bb, float* __restrict__ out)
{
    __shared__ float red[8];
    const int row = blockIdx.x;
    const int tid = threadIdx.x;
    const int lane = tid & 31, warp = tid >> 5;
    const float4 xv = ((const float4*)(Y + (long long)row * DMODEL))[tid];
    float v[4] = {xv.x, xv.y, xv.z, xv.w};

    float s = v[0] + v[1] + v[2] + v[3];
#pragma unroll
    for (int st = 16; st > 0; st >>= 1) s += __shfl_xor_sync(~0u, s, st);
    if (lane == 0) red[warp] = s;
    __syncthreads();
    if (warp == 0) {
        float t = red[lane & 7];
#pragma unroll
        for (int st = 4; st > 0; st >>= 1) t += __shfl_xor_sync(~0u, t, st);
        if (lane == 0) red[0] = t;
    }
    __syncthreads();
    const float mu = red[0] * (1.0f / DMODEL);
    __syncthreads();

    float var = 0.0f;
#pragma unroll
    for (int i = 0; i < 4; ++i) { float d = v[i] - mu; var += d * d; }
#pragma unroll
    for (int st = 16; st > 0; st >>= 1) var += __shfl_xor_sync(~0u, var, st);
    if (lane == 0) red[warp] = var;
    __syncthreads();
    if (warp == 0) {
        float t = red[lane & 7];
#pragma unroll
        for (int st = 4; st > 0; st >>= 1) t += __shfl_xor_sync(~0u, t, st);
        if (lane == 0) red[0] = t;
    }
    __syncthreads();
    const float rstd = rsqrtf(red[0] * (1.0f / DMODEL) + 1e-6f);

    const float4 g4 = ((const float4*)gg)[tid];
    const float4 b4 = ((const float4*)bb)[tid];
    float4 o;
    o.x = (v[0] - mu) * rstd * g4.x + b4.x;
    o.y = (v[1] - mu) * rstd * g4.y + b4.y;
    o.z = (v[2] - mu) * rstd * g4.z + b4.z;
    o.w = (v[3] - mu) * rstd * g4.w + b4.w;
    ((float4*)(out + (long long)row * DMODEL))[tid] = o;
}

// ---------------- launch -----------------------------------------------------
static float* symaddr(const void* sym) {
    void* p = nullptr;
    cudaGetSymbolAddress(&p, sym);
    return (float*)p;
}

extern "C" void kernel_launch(void* const* d_in, const int* in_sizes, int n_in,
                              void* d_out, int out_size)
{
    const float* q    = (const float*)d_in[0];
    const float* k    = (const float*)d_in[1];
    const float* v    = (const float*)d_in[2];
    const float* w_q  = (const float*)d_in[3];
    const float* w_k  = (const float*)d_in[4];
    const float* w_v  = (const float*)d_in[5];
    const float* w_o  = (const float*)d_in[6];
    const float* ln_g = (const float*)d_in[7];
    const float* ln_b = (const float*)d_in[8];

    float* out = (float*)d_out;
    float* attn_out = nullptr;
    const long long OUT_ELEMS  = (long long)ROWS * DMODEL;
    const long long ATTN_ELEMS = (long long)NBH * SEQ * SEQ;
    if ((long long)out_size >= OUT_ELEMS + ATTN_ELEMS)
        attn_out = out + OUT_ELEMS;

    float* Q  = symaddr(g_Q);
    float* K  = symaddr(g_K);
    float* V  = symaddr(g_V);
    float* S  = symaddr(g_S);
    float* AO = symaddr(g_AO);
    float* Y  = symaddr(g_Y);

    // 1-3. QKV projections
    dim3 gProj(DMODEL / 128, ROWS / 128, 1);
    gemm_bf16<128, false, false><<<gProj, 256>>>(q, w_q, Q, nullptr, ROWS, DMODEL, DMODEL, 0, 0, 0);
    gemm_bf16<128, false, false><<<gProj, 256>>>(k, w_k, K, nullptr, ROWS, DMODEL, DMODEL, 0, 0, 0);
    gemm_bf16<128, false, false><<<gProj, 256>>>(v, w_v, V, nullptr, ROWS, DMODEL, DMODEL, 0, 0, 0);

    // 4. scores (causal tiles only)
    dim3 gS(SEQ / 128, SEQ / 128, NBH);
    scores_bf16<<<gS, 256>>>(Q, K, S);

    // 5. softmax -> probs (straight into output attn region if present)
    float* probs = attn_out ? attn_out : S;
    softmax_kernel<<<NBH * SEQ, 256>>>(S, probs);

    // 6. PV per head, causal K-clamp
    dim3 gPV(1, SEQ / 128, NBH);
    gemm_bf16<64, true, false><<<gPV, 256>>>(probs, V, AO, nullptr, SEQ, DK, SEQ,
                                             (long long)SEQ * SEQ, HEAD_ELEMS, HEAD_ELEMS);

    // 7. output projection + residual
    gemm_bf16<128, false, true><<<gProj, 256>>>(AO, w_o, Y, q, ROWS, DMODEL, DMODEL, 0, 0, 0);

    // 8. LayerNorm -> d_out
    ln_kernel<<<ROWS, 256>>>(Y, ln_g, ln_b, out);
}